// round 14
// baseline (speedup 1.0000x reference)
#include <cuda_runtime.h>

#define B_  4
#define L_  1024
#define D_  512
#define H_  8
#define DK_ 64

// ---------------- scratch (no allocations allowed) ----------------
__device__ float g_Q [B_*L_*D_];
__device__ float g_K [B_*L_*D_];
__device__ float g_V [B_*L_*D_];
__device__ float g_QP[B_*L_*D_];
__device__ float g_KP[B_*L_*D_];
__device__ float g_AV[B_*L_*D_];
__device__ float g_g [B_*L_];

// =================================================================
// Core NN SGEMM tile: C[M,N] = A[M,512] @ W[512,N] + bias
// 128x128 tile, BK=16, 256 threads, 8x8 micro-tile (scalar FFMA).
// =================================================================
__device__ __forceinline__ void gemm_nn_core(
    const float* __restrict__ A, const float* __restrict__ W,
    const float* __restrict__ bias, float* __restrict__ C,
    float As[16][132], float Ws[16][132])
{
    const int tid = threadIdx.x;
    const int tx = tid & 15;          // n micro-group
    const int ty = tid >> 4;          // m micro-group
    const int m0 = blockIdx.y * 128, n0 = blockIdx.x * 128;

    float acc[8][8] = {};

    for (int k0 = 0; k0 < 512; k0 += 16) {
        #pragma unroll
        for (int l = 0; l < 2; l++) {
            int idx = tid + l * 256;
            int r = idx & 127;
            int c = (idx >> 7) * 4;
            float4 v = *(const float4*)(A + (size_t)(m0 + r) * 512 + k0 + c);
            As[c+0][r] = v.x; As[c+1][r] = v.y;
            As[c+2][r] = v.z; As[c+3][r] = v.w;
        }
        #pragma unroll
        for (int l = 0; l < 2; l++) {
            int idx = tid + l * 256;
            int r = idx >> 5;
            int c = (idx & 31) * 4;
            *(float4*)&Ws[r][c] = *(const float4*)(W + (size_t)(k0 + r) * 512 + n0 + c);
        }
        __syncthreads();

        #pragma unroll
        for (int kk = 0; kk < 16; kk++) {
            float a_[8], b_[8];
            float4 t;
            t = *(float4*)&As[kk][ty * 4];      a_[0]=t.x; a_[1]=t.y; a_[2]=t.z; a_[3]=t.w;
            t = *(float4*)&As[kk][ty * 4 + 64]; a_[4]=t.x; a_[5]=t.y; a_[6]=t.z; a_[7]=t.w;
            t = *(float4*)&Ws[kk][tx * 4];      b_[0]=t.x; b_[1]=t.y; b_[2]=t.z; b_[3]=t.w;
            t = *(float4*)&Ws[kk][tx * 4 + 64]; b_[4]=t.x; b_[5]=t.y; b_[6]=t.z; b_[7]=t.w;
            #pragma unroll
            for (int i = 0; i < 8; i++)
                #pragma unroll
                for (int j = 0; j < 8; j++)
                    acc[i][j] += a_[i] * b_[j];
        }
        __syncthreads();
    }

    float4 bv0 = *(const float4*)(bias + n0 + tx * 4);
    float4 bv1 = *(const float4*)(bias + n0 + tx * 4 + 64);
    #pragma unroll
    for (int i = 0; i < 8; i++) {
        int row = m0 + ((i < 4) ? (ty * 4 + i) : (64 + ty * 4 + i - 4));
        float4 o0 = make_float4(acc[i][0] + bv0.x, acc[i][1] + bv0.y,
                                acc[i][2] + bv0.z, acc[i][3] + bv0.w);
        float4 o1 = make_float4(acc[i][4] + bv1.x, acc[i][5] + bv1.y,
                                acc[i][6] + bv1.z, acc[i][7] + bv1.w);
        *(float4*)(C + (size_t)row * 512 + n0 + tx * 4)      = o0;
        *(float4*)(C + (size_t)row * 512 + n0 + tx * 4 + 64) = o1;
    }
}

struct Proj5 {
    const float* A[5];
    const float* W[5];
    const float* bias[5];
    float*       C[5];
};

__global__ __launch_bounds__(256, 2) void proj5_kernel(Proj5 p)
{
    __shared__ float As[16][132];
    __shared__ float Ws[16][132];
    const int z = blockIdx.z;
    gemm_nn_core(p.A[z], p.W[z], p.bias[z], p.C[z], As, Ws);
}

__global__ __launch_bounds__(256, 2) void dense_kernel(
    const float* __restrict__ A, const float* __restrict__ W,
    const float* __restrict__ bias, float* __restrict__ C)
{
    __shared__ float As[16][132];
    __shared__ float Ws[16][132];
    gemm_nn_core(A, W, bias, C, As, Ws);
}

// =================================================================
// m kernel: per batch  m = sigmoid( (QP @ KP^T) / sqrt(512) )
// NT GEMM 128x128, BK=16, 8x8 micro, fused sigmoid -> d_out m region
// =================================================================
__global__ __launch_bounds__(256, 2) void m_kernel(
    const float* __restrict__ QP, const float* __restrict__ KP,
    float* __restrict__ Mout)
{
    const int bz = blockIdx.z;
    const float* A  = QP + (size_t)bz * L_ * D_;
    const float* Bp = KP + (size_t)bz * L_ * D_;
    float* C = Mout + (size_t)bz * L_ * L_;

    __shared__ float As[16][132];
    __shared__ float Bs[16][132];
    const int tid = threadIdx.x;
    const int tx = tid & 15, ty = tid >> 4;
    const int m0 = blockIdx.y * 128, n0 = blockIdx.x * 128;

    float acc[8][8] = {};

    for (int k0 = 0; k0 < 512; k0 += 16) {
        #pragma unroll
        for (int l = 0; l < 2; l++) {
            int idx = tid + l * 256;
            int r = idx & 127;
            int c = (idx >> 7) * 4;
            float4 v = *(const float4*)(A + (size_t)(m0 + r) * 512 + k0 + c);
            As[c+0][r] = v.x; As[c+1][r] = v.y;
            As[c+2][r] = v.z; As[c+3][r] = v.w;
            float4 w = *(const float4*)(Bp + (size_t)(n0 + r) * 512 + k0 + c);
            Bs[c+0][r] = w.x; Bs[c+1][r] = w.y;
            Bs[c+2][r] = w.z; Bs[c+3][r] = w.w;
        }
        __syncthreads();

        #pragma unroll
        for (int kk = 0; kk < 16; kk++) {
            float a_[8], b_[8];
            float4 t;
            t = *(float4*)&As[kk][ty * 4];      a_[0]=t.x; a_[1]=t.y; a_[2]=t.z; a_[3]=t.w;
            t = *(float4*)&As[kk][ty * 4 + 64]; a_[4]=t.x; a_[5]=t.y; a_[6]=t.z; a_[7]=t.w;
            t = *(float4*)&Bs[kk][tx * 4];      b_[0]=t.x; b_[1]=t.y; b_[2]=t.z; b_[3]=t.w;
            t = *(float4*)&Bs[kk][tx * 4 + 64]; b_[4]=t.x; b_[5]=t.y; b_[6]=t.z; b_[7]=t.w;
            #pragma unroll
            for (int i = 0; i < 8; i++)
                #pragma unroll
                for (int j = 0; j < 8; j++)
                    acc[i][j] += a_[i] * b_[j];
        }
        __syncthreads();
    }

    const float sc = 0.04419417382415922f;   // 1/sqrt(512)
    #pragma unroll
    for (int i = 0; i < 8; i++) {
        int row = m0 + ((i < 4) ? (ty * 4 + i) : (64 + ty * 4 + i - 4));
        float4 o0, o1;
        o0.x = 1.0f / (1.0f + __expf(-acc[i][0] * sc));
        o0.y = 1.0f / (1.0f + __expf(-acc[i][1] * sc));
        o0.z = 1.0f / (1.0f + __expf(-acc[i][2] * sc));
        o0.w = 1.0f / (1.0f + __expf(-acc[i][3] * sc));
        o1.x = 1.0f / (1.0f + __expf(-acc[i][4] * sc));
        o1.y = 1.0f / (1.0f + __expf(-acc[i][5] * sc));
        o1.z = 1.0f / (1.0f + __expf(-acc[i][6] * sc));
        o1.w = 1.0f / (1.0f + __expf(-acc[i][7] * sc));
        *(float4*)(C + (size_t)row * L_ + n0 + tx * 4)      = o0;
        *(float4*)(C + (size_t)row * L_ + n0 + tx * 4 + 64) = o1;
    }
}

// =================================================================
// gate kernel: g = sigmoid(query @ gate_w + gate_b), one warp per row
// =================================================================
__global__ __launch_bounds__(256) void gate_kernel(
    const float* __restrict__ query, const float* __restrict__ gw,
    const float* __restrict__ gb, float* __restrict__ g)
{
    const int row  = blockIdx.x * 8 + (threadIdx.x >> 5);
    const int lane = threadIdx.x & 31;
    const float* q = query + (size_t)row * D_;
    float s = 0.f;
    #pragma unroll
    for (int k = lane; k < D_; k += 32) s += q[k] * gw[k];
    #pragma unroll
    for (int o = 16; o; o >>= 1) s += __shfl_xor_sync(0xffffffffu, s, o);
    if (lane == 0) g[row] = 1.0f / (1.0f + __expf(-(s + gb[0])));
}

// =================================================================
// Fused attention kernel: one block = (b, h, 16 query rows), 256 thr,
// 104KB smem -> 2 CTAs/SM (16 warps) for latency hiding.
// Phase1: 4q x 4k micro, 2-way d-split, partials merged through S.
// Phase2: vectorized double softmax + calibration (8 warps x 2 rows).
// Phase3: 4q x 4d micro, 4-way k-split, combined via retired KT region.
// =================================================================
#define QROWS    16
#define S_STRIDE 1032
#define QT_OFF   (QROWS * S_STRIDE)           // 16512
#define KT_OFF   (QT_OFF + 64 * 20)           // 17792
#define SMEM_FLOATS (KT_OFF + 8704)           // 26496
#define ATTN_SMEM_BYTES (SMEM_FLOATS * 4)     // 105984

__global__ __launch_bounds__(256, 2) void attn_kernel(
    const float* __restrict__ Q, const float* __restrict__ Kg,
    const float* __restrict__ Vg, const float* __restrict__ Mg,
    const float* __restrict__ gate, float* __restrict__ AV)
{
    extern __shared__ float sm[];
    float* S  = sm;              // [16][1032]
    float* QT = sm + QT_OFF;     // [64][20]  Q^T [d][q]
    float* KT = sm + KT_OFF;     // [64][132] K^T [d][k128]; then V [128][68]; then scratch
    __shared__ float rowInv[QROWS];

    const int tid = threadIdx.x;
    const int b = blockIdx.z, h = blockIdx.y, q0 = blockIdx.x * QROWS;

    const float* Qb = Q  + ((size_t)(b * L_ + q0)) * D_ + h * DK_;
    const float* Kb = Kg + (size_t)b * L_ * D_ + h * DK_;
    const float* Vb = Vg + (size_t)b * L_ * D_ + h * DK_;
    const float* Mb = Mg + (size_t)b * L_ * L_ + (size_t)q0 * L_;

    // ---- load Q tile transposed: QT[d][q] (256 float4, one per thread) ----
    {
        int r = tid & 15;
        int c = (tid >> 4) << 2;              // 0..60
        float4 v = *(const float4*)(Qb + (size_t)r * D_ + c);
        QT[(c+0)*20 + r] = v.x; QT[(c+1)*20 + r] = v.y;
        QT[(c+2)*20 + r] = v.z; QT[(c+3)*20 + r] = v.w;
    }

    // ---- phase 1: S = (Q K^T) * 1/sqrt(64), k-chunks of 128, d-split 2 ----
    {
        const int kq = tid & 31;              // k-quad (4 k each, 128 total)
        const int dh = (tid >> 5) & 1;        // d half (warp-uniform)
        const int gq = tid >> 6;              // q quad (warp-uniform)
        const int dbase = dh * 32;

        for (int k0 = 0; k0 < L_; k0 += 128) {
            // K tile 128x64 -> KT[d][k], 2048 float4 / 256 thr = 8 each
            #pragma unroll
            for (int l = 0; l < 8; l++) {
                int idx = tid + l * 256;
                int r = idx & 127;
                int c = (idx >> 7) << 2;
                float4 v = *(const float4*)(Kb + (size_t)(k0 + r) * D_ + c);
                KT[(c+0)*132 + r] = v.x; KT[(c+1)*132 + r] = v.y;
                KT[(c+2)*132 + r] = v.z; KT[(c+3)*132 + r] = v.w;
            }
            __syncthreads();

            float acc[4][4] = {};
            #pragma unroll 8
            for (int dd = 0; dd < 32; dd++) {
                const int d = dbase + dd;
                float4 a4 = *(float4*)(QT + d * 20 + gq * 4);
                float4 b4 = *(float4*)(KT + d * 132 + kq * 4);
                float a_[4] = {a4.x, a4.y, a4.z, a4.w};
                float b_[4] = {b4.x, b4.y, b4.z, b4.w};
                #pragma unroll
                for (int i = 0; i < 4; i++)
                    #pragma unroll
                    for (int j = 0; j < 4; j++)
                        acc[i][j] += a_[i] * b_[j];
            }

            // d-split merge through S: dh=1 writes raw partials first
            if (dh == 1) {
                #pragma unroll
                for (int i = 0; i < 4; i++)
                    *(float4*)(S + (gq*4 + i) * S_STRIDE + k0 + kq*4) =
                        make_float4(acc[i][0], acc[i][1], acc[i][2], acc[i][3]);
            }
            __syncthreads();
            if (dh == 0) {
                #pragma unroll
                for (int i = 0; i < 4; i++) {
                    float* p = S + (gq*4 + i) * S_STRIDE + k0 + kq*4;
                    float4 o = *(float4*)p;
                    o.x = (o.x + acc[i][0]) * 0.125f;
                    o.y = (o.y + acc[i][1]) * 0.125f;
                    o.z = (o.z + acc[i][2]) * 0.125f;
                    o.w = (o.w + acc[i][3]) * 0.125f;
                    *(float4*)p = o;
                }
            }
            __syncthreads();
        }
    }

    // ---- phase 2: softmax -> calibrate with m,g -> second softmax ----
    {
        const int warp = tid >> 5, lane = tid & 31;
        #pragma unroll
        for (int rr = 0; rr < 2; rr++) {
            const int r = warp * 2 + rr;
            float4* Srow4 = (float4*)(S + r * S_STRIDE);

            float mx = -1e30f;
            for (int i = lane; i < 256; i += 32) {
                float4 v = Srow4[i];
                mx = fmaxf(mx, fmaxf(fmaxf(v.x, v.y), fmaxf(v.z, v.w)));
            }
            #pragma unroll
            for (int o = 16; o; o >>= 1) mx = fmaxf(mx, __shfl_xor_sync(0xffffffffu, mx, o));

            float sum = 0.f;
            for (int i = lane; i < 256; i += 32) {
                float4 v = Srow4[i];
                v.x = __expf(v.x - mx); v.y = __expf(v.y - mx);
                v.z = __expf(v.z - mx); v.w = __expf(v.w - mx);
                Srow4[i] = v;
                sum += v.x + v.y + v.z + v.w;
            }
            #pragma unroll
            for (int o = 16; o; o >>= 1) sum += __shfl_xor_sync(0xffffffffu, sum, o);
            const float inv = 1.0f / sum;

            const float gq = gate[b * L_ + q0 + r];
            const float gq1 = 1.0f - gq;
            const float4* mrow4 = (const float4*)(Mb + (size_t)r * L_);
            float cmax = -1e30f;
            for (int i = lane; i < 256; i += 32) {
                float4 v = Srow4[i];
                float4 mm = mrow4[i];
                v.x *= inv * (gq + gq1 * __expf(1.0f - mm.x));
                v.y *= inv * (gq + gq1 * __expf(1.0f - mm.y));
                v.z *= inv * (gq + gq1 * __expf(1.0f - mm.z));
                v.w *= inv * (gq + gq1 * __expf(1.0f - mm.w));
                Srow4[i] = v;
                cmax = fmaxf(cmax, fmaxf(fmaxf(v.x, v.y), fmaxf(v.z, v.w)));
            }
            #pragma unroll
            for (int o = 16; o; o >>= 1) cmax = fmaxf(cmax, __shfl_xor_sync(0xffffffffu, cmax, o));

            float s2 = 0.f;
            for (int i = lane; i < 256; i += 32) {
                float4 v = Srow4[i];
                v.x = __expf(v.x - cmax); v.y = __expf(v.y - cmax);
                v.z = __expf(v.z - cmax); v.w = __expf(v.w - cmax);
                Srow4[i] = v;
                s2 += v.x + v.y + v.z + v.w;
            }
            #pragma unroll
            for (int o = 16; o; o >>= 1) s2 += __shfl_xor_sync(0xffffffffu, s2, o);
            if (lane == 0) rowInv[r] = 1.0f / s2;
        }
    }
    __syncthreads();

    // ---- phase 3: O = softmax2(P) @ V, 4q x 4d micro, 4-way k-split ----
    {
        const int gd = tid & 15;              // d quad (warp spans 16)
        const int gk = (tid >> 4) & 3;        // k split (2 values per warp)
        const int gq = tid >> 6;              // q quad (warp-uniform)

        float acc[4][4] = {};

        for (int k0 = 0; k0 < L_; k0 += 128) {
            #pragma unroll
            for (int l = 0; l < 8; l++) {
                int idx = tid + l * 256;      // V tile [128][68]
                int r = idx >> 4, c = (idx & 15) << 2;
                *(float4*)(KT + r * 68 + c) = *(const float4*)(Vb + (size_t)(k0 + r) * D_ + c);
            }
            __syncthreads();

            #pragma unroll 4
            for (int t = 0; t < 8; t++) {
                const int kb = gk * 32 + t * 4;       // this split's k-quad base
                float4 s0 = *(const float4*)(S + (gq*4 + 0) * S_STRIDE + k0 + kb);
                float4 s1 = *(const float4*)(S + (gq*4 + 1) * S_STRIDE + k0 + kb);
                float4 s2 = *(const float4*)(S + (gq*4 + 2) * S_STRIDE + k0 + kb);
                float4 s3 = *(const float4*)(S + (gq*4 + 3) * S_STRIDE + k0 + kb);
                float sa0[4] = {s0.x, s0.y, s0.z, s0.w};
                float sa1[4] = {s1.x, s1.y, s1.z, s1.w};
                float sa2[4] = {s2.x, s2.y, s2.z, s2.w};
                float sa3[4] = {s3.x, s3.y, s3.z, s3.w};
                #pragma unroll
                for (int j = 0; j < 4; j++) {
                    float4 v = *(float4*)(KT + (kb + j) * 68 + gd * 4);
                    acc[0][0] += sa0[j] * v.x; acc[0][1] += sa0[j] * v.y;
                    acc[0][2] += sa0[j] * v.z; acc[0][3] += sa0[j] * v.w;
                    acc[1][0] += sa1[j] * v.x; acc[1][1] += sa1[j] * v.y;
                    acc[1][2] += sa1[j] * v.z; acc[1][3] += sa1[j] * v.w;
                    acc[2][0] += sa2[j] * v.x; acc[2][1] += sa2[j] * v.y;
                    acc[2][2] += sa2[j] * v.z; acc[2][3] += sa2[j] * v.w;
                    acc[3][0] += sa3[j] * v.x; acc[3][1] += sa3[j] * v.y;
                    acc[3][2] += sa3[j] * v.z; acc[3][3] += sa3[j] * v.w;
                }
            }
            __syncthreads();
        }

        // combine 4 k-splits via retired KT region:
        // slot layout: ((gq*16 + gd)*3 + (gk-1)) * 17 : 16 floats + pad
        if (gk != 0) {
            float* red = KT + ((gq * 16 + gd) * 3 + (gk - 1)) * 17;
            #pragma unroll
            for (int qi = 0; qi < 4; qi++)
                #pragma unroll
                for (int j = 0; j < 4; j++)
                    red[qi * 4 + j] = acc[qi][j];
        }
        __syncthreads();
        if (gk == 0) {
            float* red = KT + (gq * 16 + gd) * 3 * 17;
            #pragma unroll
            for (int qi = 0; qi < 4; qi++) {
                const int r = gq * 4 + qi;
                const float sc = rowInv[r];
                float4 o;
                o.x = (acc[qi][0] + red[qi*4+0] + red[17 + qi*4+0] + red[34 + qi*4+0]) * sc;
                o.y = (acc[qi][1] + red[qi*4+1] + red[17 + qi*4+1] + red[34 + qi*4+1]) * sc;
                o.z = (acc[qi][2] + red[qi*4+2] + red[17 + qi*4+2] + red[34 + qi*4+2]) * sc;
                o.w = (acc[qi][3] + red[qi*4+3] + red[17 + qi*4+3] + red[34 + qi*4+3]) * sc;
                *(float4*)(AV + ((size_t)(b * L_ + q0 + r)) * D_ + h * DK_ + gd * 4) = o;
            }
        }
    }
}

// =================================================================
// launcher
// =================================================================
extern "C" void kernel_launch(void* const* d_in, const int* in_sizes, int n_in,
                              void* d_out, int out_size)
{
    const float* query   = (const float*)d_in[0];
    const float* key     = (const float*)d_in[1];
    const float* value   = (const float*)d_in[2];
    const float* wq_w    = (const float*)d_in[3];
    const float* wq_b    = (const float*)d_in[4];
    const float* wk_w    = (const float*)d_in[5];
    const float* wk_b    = (const float*)d_in[6];
    const float* wv_w    = (const float*)d_in[7];
    const float* wv_b    = (const float*)d_in[8];
    const float* dense_w = (const float*)d_in[9];
    const float* dense_b = (const float*)d_in[10];
    const float* gate_w  = (const float*)d_in[11];
    const float* gate_b  = (const float*)d_in[12];
    const float* mp_wq_w = (const float*)d_in[13];
    const float* mp_wq_b = (const float*)d_in[14];
    const float* mp_wk_w = (const float*)d_in[15];
    const float* mp_wk_b = (const float*)d_in[16];

    float* out  = (float*)d_out;                    // (B, L, D)
    float* mout = out + (size_t)B_ * L_ * D_;       // (B, L, L)

    float *Qd, *Kd, *Vd, *QPd, *KPd, *AVd, *gd;
    cudaGetSymbolAddress((void**)&Qd,  g_Q);
    cudaGetSymbolAddress((void**)&Kd,  g_K);
    cudaGetSymbolAddress((void**)&Vd,  g_V);
    cudaGetSymbolAddress((void**)&QPd, g_QP);
    cudaGetSymbolAddress((void**)&KPd, g_KP);
    cudaGetSymbolAddress((void**)&AVd, g_AV);
    cudaGetSymbolAddress((void**)&gd,  g_g);

    Proj5 p;
    p.A[0] = query; p.W[0] = wq_w;    p.bias[0] = wq_b;    p.C[0] = Qd;
    p.A[1] = key;   p.W[1] = wk_w;    p.bias[1] = wk_b;    p.C[1] = Kd;
    p.A[2] = value; p.W[2] = wv_w;    p.bias[2] = wv_b;    p.C[2] = Vd;
    p.A[3] = query; p.W[3] = mp_wq_w; p.bias[3] = mp_wq_b; p.C[3] = QPd;
    p.A[4] = key;   p.W[4] = mp_wk_w; p.bias[4] = mp_wk_b; p.C[4] = KPd;

    proj5_kernel<<<dim3(D_ / 128, (B_ * L_) / 128, 5), 256>>>(p);

    gate_kernel<<<(B_ * L_) / 8, 256>>>(query, gate_w, gate_b, gd);

    m_kernel<<<dim3(L_ / 128, L_ / 128, B_), 256>>>(QPd, KPd, mout);

    cudaFuncSetAttribute(attn_kernel,
                         cudaFuncAttributeMaxDynamicSharedMemorySize,
                         ATTN_SMEM_BYTES);
    attn_kernel<<<dim3(L_ / QROWS, H_, B_), 256, ATTN_SMEM_BYTES>>>(
        Qd, Kd, Vd, mout, gd, AVd);

    dense_kernel<<<dim3(D_ / 128, (B_ * L_) / 128), 256>>>(AVd, dense_w, dense_b, out);
}

// round 15
// speedup vs baseline: 1.3768x; 1.3768x over previous
#include <cuda_runtime.h>

#define B_  4
#define L_  1024
#define D_  512
#define H_  8
#define DK_ 64

// ---------------- scratch (no allocations allowed) ----------------
__device__ float g_Q [B_*L_*D_];
__device__ float g_K [B_*L_*D_];
__device__ float g_V [B_*L_*D_];
__device__ float g_QP[B_*L_*D_];
__device__ float g_KP[B_*L_*D_];
__device__ float g_AV[B_*L_*D_];
__device__ float g_g [B_*L_];

// ---------------- tf32 helpers ----------------
__device__ __forceinline__ float tf32r(float x) {
    unsigned u;
    asm("cvt.rna.tf32.f32 %0, %1;" : "=r"(u) : "f"(x));
    return __uint_as_float(u);
}
__device__ __forceinline__ void mma_tf32(float c[4],
    unsigned a0, unsigned a1, unsigned a2, unsigned a3,
    unsigned b0, unsigned b1)
{
    asm("mma.sync.aligned.m16n8k8.row.col.f32.tf32.tf32.f32 "
        "{%0,%1,%2,%3},{%4,%5,%6,%7},{%8,%9},{%0,%1,%2,%3};"
        : "+f"(c[0]), "+f"(c[1]), "+f"(c[2]), "+f"(c[3])
        : "r"(a0), "r"(a1), "r"(a2), "r"(a3), "r"(b0), "r"(b1));
}
#define FU(x) __float_as_uint(x)

// =================================================================
// tf32 MMA NN GEMM: C[M,N] = A[M,512] @ W[512,N] + bias (row-major)
// 128x128 tile, BK=16, 256 threads = 8 warps (2m x 4n), warp 64x32.
// =================================================================
__device__ __forceinline__ void gemm_mma_nn(
    const float* __restrict__ A, const float* __restrict__ W,
    const float* __restrict__ bias, float* __restrict__ C,
    float As[128][20], float Ws[16][136])
{
    const int tid  = threadIdx.x;
    const int lane = tid & 31, warp = tid >> 5;
    const int wm = (warp >> 2) * 64;        // 0 / 64
    const int wn = (warp & 3) * 32;         // 0..96
    const int gID = lane >> 2, tig = lane & 3;
    const int m0 = blockIdx.y * 128, n0 = blockIdx.x * 128;

    float acc[4][4][4] = {};

    for (int k0 = 0; k0 < 512; k0 += 16) {
        #pragma unroll
        for (int l = 0; l < 2; l++) {
            int idx = tid + l * 256;
            int r = idx & 127;
            int c = (idx >> 7) * 4;
            float4 v = *(const float4*)(A + (size_t)(m0 + r) * 512 + k0 + c);
            As[r][c+0] = tf32r(v.x); As[r][c+1] = tf32r(v.y);
            As[r][c+2] = tf32r(v.z); As[r][c+3] = tf32r(v.w);
        }
        #pragma unroll
        for (int l = 0; l < 2; l++) {
            int idx = tid + l * 256;
            int r = idx >> 5;                // 0..15
            int c = (idx & 31) * 4;
            float4 v = *(const float4*)(W + (size_t)(k0 + r) * 512 + n0 + c);
            Ws[r][c+0] = tf32r(v.x); Ws[r][c+1] = tf32r(v.y);
            Ws[r][c+2] = tf32r(v.z); Ws[r][c+3] = tf32r(v.w);
        }
        __syncthreads();

        #pragma unroll
        for (int kk = 0; kk < 16; kk += 8) {
            unsigned af[4][4], bf[4][2];
            #pragma unroll
            for (int i = 0; i < 4; i++) {
                int r = wm + i * 16 + gID;
                af[i][0] = FU(As[r    ][kk + tig    ]);
                af[i][1] = FU(As[r + 8][kk + tig    ]);
                af[i][2] = FU(As[r    ][kk + tig + 4]);
                af[i][3] = FU(As[r + 8][kk + tig + 4]);
            }
            #pragma unroll
            for (int j = 0; j < 4; j++) {
                int cn = wn + j * 8 + gID;
                bf[j][0] = FU(Ws[kk + tig    ][cn]);
                bf[j][1] = FU(Ws[kk + tig + 4][cn]);
            }
            #pragma unroll
            for (int i = 0; i < 4; i++)
                #pragma unroll
                for (int j = 0; j < 4; j++)
                    mma_tf32(acc[i][j], af[i][0], af[i][1], af[i][2], af[i][3],
                             bf[j][0], bf[j][1]);
        }
        __syncthreads();
    }

    #pragma unroll
    for (int i = 0; i < 4; i++) {
        #pragma unroll
        for (int j = 0; j < 4; j++) {
            int row = m0 + wm + i * 16 + gID;
            int col = n0 + wn + j * 8 + tig * 2;
            float bx = bias[col], by = bias[col + 1];
            *(float2*)(C + (size_t)row * 512 + col) =
                make_float2(acc[i][j][0] + bx, acc[i][j][1] + by);
            *(float2*)(C + (size_t)(row + 8) * 512 + col) =
                make_float2(acc[i][j][2] + bx, acc[i][j][3] + by);
        }
    }
}

struct Proj5 {
    const float* A[5];
    const float* W[5];
    const float* bias[5];
    float*       C[5];
};

__global__ __launch_bounds__(256) void proj5_kernel(Proj5 p)
{
    __shared__ float As[128][20];
    __shared__ float Ws[16][136];
    const int z = blockIdx.z;
    gemm_mma_nn(p.A[z], p.W[z], p.bias[z], p.C[z], As, Ws);
}

__global__ __launch_bounds__(256) void dense_kernel(
    const float* __restrict__ A, const float* __restrict__ W,
    const float* __restrict__ bias, float* __restrict__ C)
{
    __shared__ float As[128][20];
    __shared__ float Ws[16][136];
    gemm_mma_nn(A, W, bias, C, As, Ws);
}

// =================================================================
// m kernel (tf32 MMA NT): m = sigmoid( (QP @ KP^T) / sqrt(512) )
// 128x128 tile, BK=16, warp 64x32, fused sigmoid -> d_out m region
// =================================================================
__global__ __launch_bounds__(256) void m_kernel(
    const float* __restrict__ QP, const float* __restrict__ KP,
    float* __restrict__ Mout)
{
    const int bz = blockIdx.z;
    const float* A  = QP + (size_t)bz * L_ * D_;
    const float* Bp = KP + (size_t)bz * L_ * D_;
    float* C = Mout + (size_t)bz * L_ * L_;

    __shared__ float As[128][20];
    __shared__ float Bs[128][20];

    const int tid  = threadIdx.x;
    const int lane = tid & 31, warp = tid >> 5;
    const int wm = (warp >> 2) * 64;
    const int wn = (warp & 3) * 32;
    const int gID = lane >> 2, tig = lane & 3;
    const int m0 = blockIdx.y * 128, n0 = blockIdx.x * 128;

    float acc[4][4][4] = {};

    for (int k0 = 0; k0 < 512; k0 += 16) {
        #pragma unroll
        for (int l = 0; l < 2; l++) {
            int idx = tid + l * 256;
            int r = idx & 127;
            int c = (idx >> 7) * 4;
            float4 v = *(const float4*)(A + (size_t)(m0 + r) * 512 + k0 + c);
            As[r][c+0] = tf32r(v.x); As[r][c+1] = tf32r(v.y);
            As[r][c+2] = tf32r(v.z); As[r][c+3] = tf32r(v.w);
            float4 w = *(const float4*)(Bp + (size_t)(n0 + r) * 512 + k0 + c);
            Bs[r][c+0] = tf32r(w.x); Bs[r][c+1] = tf32r(w.y);
            Bs[r][c+2] = tf32r(w.z); Bs[r][c+3] = tf32r(w.w);
        }
        __syncthreads();

        #pragma unroll
        for (int kk = 0; kk < 16; kk += 8) {
            unsigned af[4][4], bf[4][2];
            #pragma unroll
            for (int i = 0; i < 4; i++) {
                int r = wm + i * 16 + gID;
                af[i][0] = FU(As[r    ][kk + tig    ]);
                af[i][1] = FU(As[r + 8][kk + tig    ]);
                af[i][2] = FU(As[r    ][kk + tig + 4]);
                af[i][3] = FU(As[r + 8][kk + tig + 4]);
            }
            #pragma unroll
            for (int j = 0; j < 4; j++) {
                int rn = wn + j * 8 + gID;
                bf[j][0] = FU(Bs[rn][kk + tig    ]);
                bf[j][1] = FU(Bs[rn][kk + tig + 4]);
            }
            #pragma unroll
            for (int i = 0; i < 4; i++)
                #pragma unroll
                for (int j = 0; j < 4; j++)
                    mma_tf32(acc[i][j], af[i][0], af[i][1], af[i][2], af[i][3],
                             bf[j][0], bf[j][1]);
        }
        __syncthreads();
    }

    const float sc = 0.04419417382415922f;   // 1/sqrt(512)
    #pragma unroll
    for (int i = 0; i < 4; i++) {
        #pragma unroll
        for (int j = 0; j < 4; j++) {
            int row = m0 + wm + i * 16 + gID;
            int col = n0 + wn + j * 8 + tig * 2;
            float2 o0, o1;
            o0.x = 1.0f / (1.0f + __expf(-acc[i][j][0] * sc));
            o0.y = 1.0f / (1.0f + __expf(-acc[i][j][1] * sc));
            o1.x = 1.0f / (1.0f + __expf(-acc[i][j][2] * sc));
            o1.y = 1.0f / (1.0f + __expf(-acc[i][j][3] * sc));
            *(float2*)(C + (size_t)row * L_ + col)       = o0;
            *(float2*)(C + (size_t)(row + 8) * L_ + col) = o1;
        }
    }
}

// =================================================================
// gate kernel: g = sigmoid(query @ gate_w + gate_b), one warp per row
// =================================================================
__global__ __launch_bounds__(256) void gate_kernel(
    const float* __restrict__ query, const float* __restrict__ gw,
    const float* __restrict__ gb, float* __restrict__ g)
{
    const int row  = blockIdx.x * 8 + (threadIdx.x >> 5);
    const int lane = threadIdx.x & 31;
    const float* q = query + (size_t)row * D_;
    float s = 0.f;
    #pragma unroll
    for (int k = lane; k < D_; k += 32) s += q[k] * gw[k];
    #pragma unroll
    for (int o = 16; o; o >>= 1) s += __shfl_xor_sync(0xffffffffu, s, o);
    if (lane == 0) g[row] = 1.0f / (1.0f + __expf(-(s + gb[0])));
}

// =================================================================
// Fused attention kernel (R13 best config): one block = (b,h,32 q rows),
// 256 threads, 208KB smem.
// Phase1: 4q x 8k micro.  Phase2: vectorized double softmax.
// Phase3: 4q x 4d micro, 2-way k-split via retired QT region.
// =================================================================
#define S_STRIDE 1032
#define QT_OFF   (32 * S_STRIDE)              // 33024
#define KT_OFF   (QT_OFF + 64 * 36)           // 35328
#define SMEM_FLOATS (KT_OFF + 64 * 260)       // 51968
#define ATTN_SMEM_BYTES (SMEM_FLOATS * 4)     // 207872

__global__ __launch_bounds__(256) void attn_kernel(
    const float* __restrict__ Q, const float* __restrict__ Kg,
    const float* __restrict__ Vg, const float* __restrict__ Mg,
    const float* __restrict__ gate, float* __restrict__ AV)
{
    extern __shared__ float sm[];
    float* S  = sm;              // [32][1032]
    float* QT = sm + QT_OFF;     // [64][36]  Q^T [d][q]; later reduce scratch
    float* KT = sm + KT_OFF;     // [64][260] K^T [d][k256]; later V [128][68]
    __shared__ float rowInv[32];

    const int tid = threadIdx.x;
    const int b = blockIdx.z, h = blockIdx.y, q0 = blockIdx.x * 32;

    const float* Qb = Q  + ((size_t)(b * L_ + q0)) * D_ + h * DK_;
    const float* Kb = Kg + (size_t)b * L_ * D_ + h * DK_;
    const float* Vb = Vg + (size_t)b * L_ * D_ + h * DK_;
    const float* Mb = Mg + (size_t)b * L_ * L_ + (size_t)q0 * L_;

    // ---- load Q tile transposed: QT[d][q], conflict-free STS ----
    #pragma unroll
    for (int l = 0; l < 2; l++) {
        int idx = tid + l * 256;              // 512 float4 : 32 rows x 16 chunks
        int r = idx & 31;
        int c = (idx >> 5) * 4;
        float4 v = *(const float4*)(Qb + (size_t)r * D_ + c);
        QT[(c+0)*36 + r] = v.x; QT[(c+1)*36 + r] = v.y;
        QT[(c+2)*36 + r] = v.z; QT[(c+3)*36 + r] = v.w;
    }

    // ---- phase 1: S = (Q K^T) * 1/sqrt(64), k-chunks of 256 ----
    {
        const int tx = tid & 31;              // k micro-group (8 k each)
        const int ty = tid >> 5;              // q micro-group (4 q each)
        for (int k0 = 0; k0 < L_; k0 += 256) {
            #pragma unroll
            for (int l = 0; l < 16; l++) {
                int idx = tid + l * 256;
                int r = idx & 255;
                int c = (idx >> 8) * 4;
                float4 v = *(const float4*)(Kb + (size_t)(k0 + r) * D_ + c);
                KT[(c+0)*260 + r] = v.x; KT[(c+1)*260 + r] = v.y;
                KT[(c+2)*260 + r] = v.z; KT[(c+3)*260 + r] = v.w;
            }
            __syncthreads();

            float acc[4][8] = {};
            #pragma unroll 8
            for (int d = 0; d < 64; d++) {
                float4 a4 = *(float4*)(QT + d * 36 + ty * 4);
                float4 b0 = *(float4*)(KT + d * 260 + tx * 4);
                float4 b1 = *(float4*)(KT + d * 260 + 128 + tx * 4);
                float a_[4] = {a4.x, a4.y, a4.z, a4.w};
                float b_[8] = {b0.x, b0.y, b0.z, b0.w, b1.x, b1.y, b1.z, b1.w};
                #pragma unroll
                for (int i = 0; i < 4; i++)
                    #pragma unroll
                    for (int j = 0; j < 8; j++)
                        acc[i][j] += a_[i] * b_[j];
            }
            #pragma unroll
            for (int i = 0; i < 4; i++) {
                float* Srow = S + (ty * 4 + i) * S_STRIDE + k0;
                float4 o0 = make_float4(acc[i][0]*0.125f, acc[i][1]*0.125f,
                                        acc[i][2]*0.125f, acc[i][3]*0.125f);
                float4 o1 = make_float4(acc[i][4]*0.125f, acc[i][5]*0.125f,
                                        acc[i][6]*0.125f, acc[i][7]*0.125f);
                *(float4*)(Srow + tx * 4)       = o0;
                *(float4*)(Srow + 128 + tx * 4) = o1;
            }
            __syncthreads();
        }
    }

    // ---- phase 2: softmax -> calibrate with m,g -> second softmax ----
    {
        const int warp = tid >> 5, lane = tid & 31;
        #pragma unroll
        for (int rr = 0; rr < 4; rr++) {
            const int r = warp * 4 + rr;
            float4* Srow4 = (float4*)(S + r * S_STRIDE);

            float mx = -1e30f;
            for (int i = lane; i < 256; i += 32) {
                float4 v = Srow4[i];
                mx = fmaxf(mx, fmaxf(fmaxf(v.x, v.y), fmaxf(v.z, v.w)));
            }
            #pragma unroll
            for (int o = 16; o; o >>= 1) mx = fmaxf(mx, __shfl_xor_sync(0xffffffffu, mx, o));

            float sum = 0.f;
            for (int i = lane; i < 256; i += 32) {
                float4 v = Srow4[i];
                v.x = __expf(v.x - mx); v.y = __expf(v.y - mx);
                v.z = __expf(v.z - mx); v.w = __expf(v.w - mx);
                Srow4[i] = v;
                sum += v.x + v.y + v.z + v.w;
            }
            #pragma unroll
            for (int o = 16; o; o >>= 1) sum += __shfl_xor_sync(0xffffffffu, sum, o);
            const float inv = 1.0f / sum;

            const float gq = gate[b * L_ + q0 + r];
            const float gq1 = 1.0f - gq;
            const float4* mrow4 = (const float4*)(Mb + (size_t)r * L_);
            float cmax = -1e30f;
            for (int i = lane; i < 256; i += 32) {
                float4 v = Srow4[i];
                float4 mm = mrow4[i];
                v.x *= inv * (gq + gq1 * __expf(1.0f - mm.x));
                v.y *= inv * (gq + gq1 * __expf(1.0f - mm.y));
                v.z *= inv * (gq + gq1 * __expf(1.0f - mm.z));
                v.w *= inv * (gq + gq1 * __expf(1.0f - mm.w));
                Srow4[i] = v;
                cmax = fmaxf(cmax, fmaxf(fmaxf(v.x, v.y), fmaxf(v.z, v.w)));
            }
            #pragma unroll
            for (int o = 16; o; o >>= 1) cmax = fmaxf(cmax, __shfl_xor_sync(0xffffffffu, cmax, o));

            float s2 = 0.f;
            for (int i = lane; i < 256; i += 32) {
                float4 v = Srow4[i];
                v.x = __expf(v.x - cmax); v.y = __expf(v.y - cmax);
                v.z = __expf(v.z - cmax); v.w = __expf(v.w - cmax);
                Srow4[i] = v;
                s2 += v.x + v.y + v.z + v.w;
            }
            #pragma unroll
            for (int o = 16; o; o >>= 1) s2 += __shfl_xor_sync(0xffffffffu, s2, o);
            if (lane == 0) rowInv[r] = 1.0f / s2;
        }
    }
    __syncthreads();

    // ---- phase 3: O = softmax2(P) @ V ----
    // 4q x 4d micro, 2-way k-split. Warp = (16 d-groups x 2 k-splits),
    // q uniform per warp -> S float4 loads broadcast; V conflict-free.
    {
        const int gd = tid & 15;              // d quad
        const int gk = (tid >> 4) & 1;        // k half
        const int gq = tid >> 5;              // q quad (warp-uniform)

        float acc[4][4] = {};

        for (int k0 = 0; k0 < L_; k0 += 128) {
            #pragma unroll
            for (int l = 0; l < 8; l++) {
                int idx = tid + l * 256;      // V tile [128][68]
                int r = idx >> 4, c = (idx & 15) << 2;
                *(float4*)(KT + r * 68 + c) = *(const float4*)(Vb + (size_t)(k0 + r) * D_ + c);
            }
            __syncthreads();

            #pragma unroll 4
            for (int t = 0; t < 16; t++) {
                const int kb = t * 8 + gk * 4;
                float4 s0 = *(const float4*)(S + (gq*4 + 0) * S_STRIDE + k0 + kb);
                float4 s1 = *(const float4*)(S + (gq*4 + 1) * S_STRIDE + k0 + kb);
                float4 s2 = *(const float4*)(S + (gq*4 + 2) * S_STRIDE + k0 + kb);
                float4 s3 = *(const float4*)(S + (gq*4 + 3) * S_STRIDE + k0 + kb);
                float sa0[4] = {s0.x, s0.y, s0.z, s0.w};
                float sa1[4] = {s1.x, s1.y, s1.z, s1.w};
                float sa2[4] = {s2.x, s2.y, s2.z, s2.w};
                float sa3[4] = {s3.x, s3.y, s3.z, s3.w};
                #pragma unroll
                for (int j = 0; j < 4; j++) {
                    float4 v = *(float4*)(KT + (kb + j) * 68 + gd * 4);
                    acc[0][0] += sa0[j] * v.x; acc[0][1] += sa0[j] * v.y;
                    acc[0][2] += sa0[j] * v.z; acc[0][3] += sa0[j] * v.w;
                    acc[1][0] += sa1[j] * v.x; acc[1][1] += sa1[j] * v.y;
                    acc[1][2] += sa1[j] * v.z; acc[1][3] += sa1[j] * v.w;
                    acc[2][0] += sa2[j] * v.x; acc[2][1] += sa2[j] * v.y;
                    acc[2][2] += sa2[j] * v.z; acc[2][3] += sa2[j] * v.w;
                    acc[3][0] += sa3[j] * v.x; acc[3][1] += sa3[j] * v.y;
                    acc[3][2] += sa3[j] * v.z; acc[3][3] += sa3[j] * v.w;
                }
            }
            __syncthreads();
        }

        // combine the two k-halves through retired QT region (stride-17 pad)
        const int p = gq * 16 + gd;           // 0..127
        float* red = QT + p * 17;
        if (gk == 1) {
            #pragma unroll
            for (int qi = 0; qi < 4; qi++)
                #pragma unroll
                for (int j = 0; j < 4; j++)
                    red[qi * 4 + j] = acc[qi][j];
        }
        __syncthreads();
        if (gk == 0) {
            #pragma unroll
            for (int qi = 0; qi < 4; qi++) {
                const int r = gq * 4 + qi;
                const float sc = rowInv[r];
                float4 o;
                o.x = (acc[qi][0] + red[qi*4 + 0]) * sc;
                o.y = (acc[qi][1] + red[qi*4 + 1]) * sc;
                o.z = (acc[qi][2] + red[qi*4 + 2]) * sc;
                o.w = (acc[qi][3] + red[qi*4 + 3]) * sc;
                *(float4*)(AV + ((size_t)(b * L_ + q0 + r)) * D_ + h * DK_ + gd * 4) = o;
            }
        }
    }
}

// =================================================================
// launcher
// =================================================================
extern "C" void kernel_launch(void* const* d_in, const int* in_sizes, int n_in,
                              void* d_out, int out_size)
{
    const float* query   = (const float*)d_in[0];
    const float* key     = (const float*)d_in[1];
    const float* value   = (const float*)d_in[2];
    const float* wq_w    = (const float*)d_in[3];
    const float* wq_b    = (const float*)d_in[4];
    const float* wk_w    = (const float*)d_in[5];
    const float* wk_b    = (const float*)d_in[6];
    const float* wv_w    = (const float*)d_in[7];
    const float* wv_b    = (const float*)d_in[8];
    const float* dense_w = (const float*)d_in[9];
    const float* dense_b = (const float*)d_in[10];
    const float* gate_w  = (const float*)d_in[11];
    const float* gate_b  = (const float*)d_in[12];
    const float* mp_wq_w = (const float*)d_in[13];
    const float* mp_wq_b = (const float*)d_in[14];
    const float* mp_wk_w = (const float*)d_in[15];
    const float* mp_wk_b = (const float*)d_in[16];

    float* out  = (float*)d_out;                    // (B, L, D)
    float* mout = out + (size_t)B_ * L_ * D_;       // (B, L, L)

    float *Qd, *Kd, *Vd, *QPd, *KPd, *AVd, *gd;
    cudaGetSymbolAddress((void**)&Qd,  g_Q);
    cudaGetSymbolAddress((void**)&Kd,  g_K);
    cudaGetSymbolAddress((void**)&Vd,  g_V);
    cudaGetSymbolAddress((void**)&QPd, g_QP);
    cudaGetSymbolAddress((void**)&KPd, g_KP);
    cudaGetSymbolAddress((void**)&AVd, g_AV);
    cudaGetSymbolAddress((void**)&gd,  g_g);

    Proj5 p;
    p.A[0] = query; p.W[0] = wq_w;    p.bias[0] = wq_b;    p.C[0] = Qd;
    p.A[1] = key;   p.W[1] = wk_w;    p.bias[1] = wk_b;    p.C[1] = Kd;
    p.A[2] = value; p.W[2] = wv_w;    p.bias[2] = wv_b;    p.C[2] = Vd;
    p.A[3] = query; p.W[3] = mp_wq_w; p.bias[3] = mp_wq_b; p.C[3] = QPd;
    p.A[4] = key;   p.W[4] = mp_wk_w; p.bias[4] = mp_wk_b; p.C[4] = KPd;

    proj5_kernel<<<dim3(D_ / 128, (B_ * L_) / 128, 5), 256>>>(p);

    gate_kernel<<<(B_ * L_) / 8, 256>>>(query, gate_w, gate_b, gd);

    m_kernel<<<dim3(L_ / 128, L_ / 128, B_), 256>>>(QPd, KPd, mout);

    cudaFuncSetAttribute(attn_kernel,
                         cudaFuncAttributeMaxDynamicSharedMemorySize,
                         ATTN_SMEM_BYTES);
    attn_kernel<<<dim3(L_ / 32, H_, B_), 256, ATTN_SMEM_BYTES>>>(
        Qd, Kd, Vd, mout, gd, AVd);

    dense_kernel<<<dim3(D_ / 128, (B_ * L_) / 128), 256>>>(AVd, dense_w, dense_b, out);
}